// round 6
// baseline (speedup 1.0000x reference)
#include <cuda_runtime.h>
#include <cstdint>

// Problem dims (fixed by dataset)
constexpr int B = 4, N = 2048, F = 128, H = 4, D = 32;
constexpr int MT = 64;                  // m rows per attn block
constexpr int KT = 32;                  // k (node) cols per tile
constexpr int HHSTR = 40;               // Hs row stride (words); 40%32==8 -> conflict-free B frags
constexpr float LOG2E = 1.4426950408889634f;

// Scratch (device globals: no allocation allowed)
__device__ __align__(16) float g_h[B * H * N * D];   // [bh][n][d]
__device__ float g_al[B * H * N];                    // pre-scaled by log2e
__device__ float g_ar[B * H * N];                    // pre-scaled by log2e
__device__ float g_armax[B * H];
__device__ unsigned g_bits[N * (N / 32)];            // adjacency bitmask

// ---------------------------------------------------------------------------
// helpers
// ---------------------------------------------------------------------------
__device__ __forceinline__ float ex2f(float x) {
    float r; asm("ex2.approx.f32 %0, %1;" : "=f"(r) : "f"(x)); return r;
}
__device__ __forceinline__ uint32_t tf32u(float x) {   // round-to-nearest tf32
    uint32_t u; asm("cvt.rna.tf32.f32 %0, %1;" : "=r"(u) : "f"(x));
    return u;
}
__device__ __forceinline__ void ffma2(unsigned long long& d,
                                      unsigned long long a,
                                      unsigned long long b) {
    asm("fma.rn.f32x2 %0, %1, %2, %0;" : "+l"(d) : "l"(a), "l"(b));
}
__device__ __forceinline__ unsigned long long pk2(float lo, float hi) {
    unsigned long long r;
    asm("mov.b64 %0, {%1, %2};" : "=l"(r)
        : "r"(__float_as_uint(lo)), "r"(__float_as_uint(hi)));
    return r;
}
__device__ __forceinline__ void upk2(unsigned long long v, float& lo, float& hi) {
    unsigned a, b;
    asm("mov.b64 {%0, %1}, %2;" : "=r"(a), "=r"(b) : "l"(v));
    lo = __uint_as_float(a); hi = __uint_as_float(b);
}
__device__ __forceinline__ void mma_tf32(float c[4], uint32_t a0, uint32_t a1,
                                         uint32_t a2, uint32_t a3,
                                         uint32_t b0, uint32_t b1) {
    asm volatile(
        "mma.sync.aligned.m16n8k8.row.col.f32.tf32.tf32.f32 "
        "{%0,%1,%2,%3}, {%4,%5,%6,%7}, {%8,%9}, {%0,%1,%2,%3};"
        : "+f"(c[0]), "+f"(c[1]), "+f"(c[2]), "+f"(c[3])
        : "r"(a0), "r"(a1), "r"(a2), "r"(a3), "r"(b0), "r"(b1));
}

// ---------------------------------------------------------------------------
// Kernel 0: pack adjacency (float 0/1) into bitmask. Warp = half a row.
// ---------------------------------------------------------------------------
__global__ __launch_bounds__(256) void pack_adj(const float* __restrict__ adj) {
    int warp = threadIdx.x >> 5, lane = threadIdx.x & 31;
    int m = blockIdx.x * 4 + (warp >> 1);
    int hf = warp & 1;
    const float* row = adj + (size_t)m * N + hf * (N / 2);
    unsigned* dst = g_bits + m * (N / 32) + hf * (N / 64);
    #pragma unroll 8
    for (int g = 0; g < N / 64; ++g) {
        float v = row[g * 32 + lane];
        unsigned word = __ballot_sync(0xFFFFFFFFu, v > 0.5f);
        if (lane == 0) dst[g] = word;
    }
}

// ---------------------------------------------------------------------------
// Kernel 1: h = x@W ; al/ar = (h.aL)*log2e, (h.aR)*log2e
// block = (b, 16 n). 128 threads = (head, d). x staged TRANSPOSED, f32x2 math.
// ---------------------------------------------------------------------------
__global__ __launch_bounds__(128) void project(const float* __restrict__ x,
                                               const float* __restrict__ Wm,
                                               const float* __restrict__ aL,
                                               const float* __restrict__ aR) {
    __shared__ __align__(16) float xs[F * 16];   // [f][n] transposed, 8KB
    const int b = blockIdx.x >> 7;
    const int n0 = (blockIdx.x & 127) * 16;
    const int tid = threadIdx.x;

    {   // load x tile transposed
        const float4* xr = (const float4*)(x + ((size_t)b * N + n0) * F);
        #pragma unroll
        for (int i = tid; i < 16 * (F / 4); i += 128) {
            int n = i >> 5, fq = i & 31;            // F/4 = 32
            float4 v = xr[(size_t)n * 32 + fq];
            xs[(fq * 4 + 0) * 16 + n] = v.x;
            xs[(fq * 4 + 1) * 16 + n] = v.y;
            xs[(fq * 4 + 2) * 16 + n] = v.z;
            xs[(fq * 4 + 3) * 16 + n] = v.w;
        }
    }
    __syncthreads();

    const int hh = tid >> 5, d = tid & 31;
    unsigned long long accp[8];
    #pragma unroll
    for (int i = 0; i < 8; ++i) accp[i] = 0ull;

    const float* Wp = Wm + (size_t)(hh * F) * D + d;
    #pragma unroll 4
    for (int f = 0; f < F; ++f) {
        float w = __ldg(Wp + (size_t)f * D);
        unsigned long long wp = pk2(w, w);
        const ulonglong2* xv = (const ulonglong2*)(xs + f * 16);
        #pragma unroll
        for (int q = 0; q < 4; ++q) {
            ulonglong2 u = xv[q];
            ffma2(accp[q * 2 + 0], u.x, wp);
            ffma2(accp[q * 2 + 1], u.y, wp);
        }
    }

    const float aLd = aL[hh * D + d];
    const float aRd = aR[hh * D + d];
    const size_t base = (size_t)(b * H + hh) * N + n0;
    #pragma unroll 2
    for (int i = 0; i < 8; ++i) {
        float a0, a1;
        upk2(accp[i], a0, a1);
        int n_0 = 2 * i, n_1 = 2 * i + 1;
        g_h[(base + n_0) * D + d] = a0;
        g_h[(base + n_1) * D + d] = a1;
        float l0 = a0 * aLd, r0 = a0 * aRd;
        float l1 = a1 * aLd, r1 = a1 * aRd;
        #pragma unroll
        for (int o = 16; o; o >>= 1) {
            l0 += __shfl_xor_sync(0xFFFFFFFFu, l0, o);
            r0 += __shfl_xor_sync(0xFFFFFFFFu, r0, o);
            l1 += __shfl_xor_sync(0xFFFFFFFFu, l1, o);
            r1 += __shfl_xor_sync(0xFFFFFFFFu, r1, o);
        }
        if (d == 0) {
            g_al[base + n_0] = l0 * LOG2E;  g_ar[base + n_0] = r0 * LOG2E;
            g_al[base + n_1] = l1 * LOG2E;  g_ar[base + n_1] = r1 * LOG2E;
        }
    }
}

// ---------------------------------------------------------------------------
// Kernel 1.5: per-(b,h) max over (scaled) ar
// ---------------------------------------------------------------------------
__global__ void armax_k() {
    __shared__ float red[256];
    int bh = blockIdx.x, tid = threadIdx.x;
    float m = -1e30f;
    for (int n = tid; n < N; n += 256) m = fmaxf(m, g_ar[bh * N + n]);
    red[tid] = m;
    __syncthreads();
    for (int s = 128; s; s >>= 1) {
        if (tid < s) red[tid] = fmaxf(red[tid], red[tid + s]);
        __syncthreads();
    }
    if (tid == 0) g_armax[bh] = red[0];
}

// ---------------------------------------------------------------------------
// Kernel 2: fused masked-softmax attention via mma.sync m16n8k8 tf32.
// Block = (b,h, 64 m rows). 8 warps. Split-K: warps 0-3 (half 0) handle
// tiles 0..31, warps 4-7 (half 1) tiles 32..63, same rows. Double-buffered
// per-half H staging, ONE sync per tile. Final C/S cross-half reduction in
// SMEM, then epilogue by half 0.
// ---------------------------------------------------------------------------
__global__ __launch_bounds__(256) void attn(const float* __restrict__ bias,
                                            float* __restrict__ out) {
    __shared__ __align__(16) float Hs[2][2][32 * HHSTR];   // [half][stage] 20KB
    __shared__ float ar_s[2][2][KT];
    __shared__ float Cred[4][16][32];                      // 8KB
    __shared__ float Sred[4][16];

    const int tid = threadIdx.x, lane = tid & 31, wid = tid >> 5;
    const int gID = lane >> 2, tIG = lane & 3;
    const int half = wid >> 2, w4 = wid & 3;
    const int bh = blockIdx.y, b = bh >> 2, h = bh & 3;
    const int m0 = blockIdx.x * MT;

    // this thread's two rows (A-fragment rows gID, gID+8 of warp's 16)
    const int gm0 = m0 + w4 * 16 + gID;
    const int gm1 = gm0 + 8;

    float al0, al1, M0, M1;
    {
        const float armax = g_armax[bh];
        al0 = g_al[(size_t)bh * N + gm0];
        al1 = g_al[(size_t)bh * N + gm1];
        float t0 = al0 + armax, t1 = al1 + armax;
        M0 = fmaxf(t0, 0.2f * t0);    // leaky upper bound (monotone)
        M1 = fmaxf(t1, 0.2f * t1);
    }
    float S0 = 0.f, S1 = 0.f;
    float c[4][4];
    #pragma unroll
    for (int nt = 0; nt < 4; ++nt)
        #pragma unroll
        for (int i = 0; i < 4; ++i) c[nt][i] = 0.f;

    const float* hb = g_h + (size_t)bh * N * D;
    const float* arp = g_ar + (size_t)bh * N;
    const unsigned* bp0 = g_bits + (size_t)gm0 * (N / 32);
    const unsigned* bp1 = g_bits + (size_t)gm1 * (N / 32);

    // staging map: 128 threads per half stage 32 rows x 32 floats
    const int tid128 = tid & 127;
    const int srow = tid128 >> 2, sseg = tid128 & 3;
    float* HsH = Hs[half][0];
    float* arH = ar_s[half][0];
    const int t_base = half * 32;    // this half's first tile

    // ---- prologue: stage tile t_base into buffer 0 ----
    {
        const float* src = hb + (size_t)(t_base * 32 + srow) * D;
        float4 v0 = *(const float4*)(src + sseg * 4);
        float4 v1 = *(const float4*)(src + (sseg + 4) * 4);
        v0.x = __uint_as_float(tf32u(v0.x)); v0.y = __uint_as_float(tf32u(v0.y));
        v0.z = __uint_as_float(tf32u(v0.z)); v0.w = __uint_as_float(tf32u(v0.w));
        v1.x = __uint_as_float(tf32u(v1.x)); v1.y = __uint_as_float(tf32u(v1.y));
        v1.z = __uint_as_float(tf32u(v1.z)); v1.w = __uint_as_float(tf32u(v1.w));
        *(float4*)&HsH[srow * HHSTR + sseg * 4] = v0;
        *(float4*)&HsH[srow * HHSTR + (sseg + 4) * 4] = v1;
        if (tid128 < KT) arH[tid128] = __ldg(arp + t_base * 32 + tid128);
    }
    __syncthreads();

    for (int i = 0; i < 32; ++i) {
        const int s = i & 1;
        // ---- stage next tile into other buffer ----
        if (i + 1 < 32) {
            const int tn = t_base + i + 1;
            const float* src = hb + (size_t)(tn * 32 + srow) * D;
            float4 v0 = *(const float4*)(src + sseg * 4);
            float4 v1 = *(const float4*)(src + (sseg + 4) * 4);
            v0.x = __uint_as_float(tf32u(v0.x)); v0.y = __uint_as_float(tf32u(v0.y));
            v0.z = __uint_as_float(tf32u(v0.z)); v0.w = __uint_as_float(tf32u(v0.w));
            v1.x = __uint_as_float(tf32u(v1.x)); v1.y = __uint_as_float(tf32u(v1.y));
            v1.z = __uint_as_float(tf32u(v1.z)); v1.w = __uint_as_float(tf32u(v1.w));
            float* dst = Hs[half][s ^ 1];
            *(float4*)&dst[srow * HHSTR + sseg * 4] = v0;
            *(float4*)&dst[srow * HHSTR + (sseg + 4) * 4] = v1;
            if (tid128 < KT)
                ar_s[half][s ^ 1][tid128] = __ldg(arp + tn * 32 + tid128);
        }
        // ---- compute on current buffer ----
        const int tt = t_base + i;
        const unsigned w0 = __ldg(bp0 + tt);
        const unsigned w1 = __ldg(bp1 + tt);
        const float* hs = Hs[half][s];
        const float* ars = ar_s[half][s];

        #pragma unroll
        for (int kc = 0; kc < 4; ++kc) {
            const int cA = kc * 8 + tIG;
            const int cB = cA + 4;
            const float arA = ars[cA];
            const float arB = ars[cB];

            float t00 = al0 + arA, t10 = al1 + arA;
            float t01 = al0 + arB, t11 = al1 + arB;
            float e00 = ex2f(fmaxf(t00, 0.2f * t00) - M0);
            float e10 = ex2f(fmaxf(t10, 0.2f * t10) - M1);
            float e01 = ex2f(fmaxf(t01, 0.2f * t01) - M0);
            float e11 = ex2f(fmaxf(t11, 0.2f * t11) - M1);
            e00 = (w0 >> cA) & 1u ? e00 : 0.f;
            e10 = (w1 >> cA) & 1u ? e10 : 0.f;
            e01 = (w0 >> cB) & 1u ? e01 : 0.f;
            e11 = (w1 >> cB) & 1u ? e11 : 0.f;
            uint32_t a0 = tf32u(e00), a1 = tf32u(e10);
            uint32_t a2 = tf32u(e01), a3 = tf32u(e11);
            S0 += __uint_as_float(a0) + __uint_as_float(a2);
            S1 += __uint_as_float(a1) + __uint_as_float(a3);

            const float* hA = hs + cA * HHSTR + gID;
            const float* hB = hs + cB * HHSTR + gID;
            #pragma unroll
            for (int nt = 0; nt < 4; ++nt) {
                uint32_t b0 = __float_as_uint(hA[nt * 8]);
                uint32_t b1 = __float_as_uint(hB[nt * 8]);
                mma_tf32(c[nt], a0, a1, a2, a3, b0, b1);
            }
        }
        __syncthreads();
    }

    // ---- reduce S over the quad (lanes sharing gID) ----
    S0 += __shfl_xor_sync(0xFFFFFFFFu, S0, 1);
    S0 += __shfl_xor_sync(0xFFFFFFFFu, S0, 2);
    S1 += __shfl_xor_sync(0xFFFFFFFFu, S1, 1);
    S1 += __shfl_xor_sync(0xFFFFFFFFu, S1, 2);

    // ---- cross-half reduction ----
    if (half == 1) {
        #pragma unroll
        for (int nt = 0; nt < 4; ++nt) {
            *(float2*)&Cred[w4][gID][nt * 8 + tIG * 2]     = make_float2(c[nt][0], c[nt][1]);
            *(float2*)&Cred[w4][gID + 8][nt * 8 + tIG * 2] = make_float2(c[nt][2], c[nt][3]);
        }
        if (tIG == 0) { Sred[w4][gID] = S0; Sred[w4][gID + 8] = S1; }
    }
    __syncthreads();
    if (half == 1) return;

    S0 += Sred[w4][gID];
    S1 += Sred[w4][gID + 8];
    const float inv0 = 1.f / S0, inv1 = 1.f / S1;

    // ---- epilogue: /S, +bias, ELU, store (B,N,H*D) ----
    float* o0 = out + ((size_t)b * N + gm0) * (H * D) + h * D + tIG * 2;
    float* o1 = out + ((size_t)b * N + gm1) * (H * D) + h * D + tIG * 2;
    const float* bp = bias + h * D + tIG * 2;
    #pragma unroll
    for (int nt = 0; nt < 4; ++nt) {
        float2 p0 = *(float2*)&Cred[w4][gID][nt * 8 + tIG * 2];
        float2 p1 = *(float2*)&Cred[w4][gID + 8][nt * 8 + tIG * 2];
        float2 bb = *(const float2*)(bp + nt * 8);
        float v00 = (c[nt][0] + p0.x) * inv0 + bb.x;
        float v01 = (c[nt][1] + p0.y) * inv0 + bb.y;
        float v10 = (c[nt][2] + p1.x) * inv1 + bb.x;
        float v11 = (c[nt][3] + p1.y) * inv1 + bb.y;
        float2 r0, r1;
        r0.x = v00 > 0.f ? v00 : expm1f(v00);
        r0.y = v01 > 0.f ? v01 : expm1f(v01);
        r1.x = v10 > 0.f ? v10 : expm1f(v10);
        r1.y = v11 > 0.f ? v11 : expm1f(v11);
        *(float2*)(o0 + nt * 8) = r0;
        *(float2*)(o1 + nt * 8) = r1;
    }
}

// ---------------------------------------------------------------------------
extern "C" void kernel_launch(void* const* d_in, const int* in_sizes, int n_in,
                              void* d_out, int out_size) {
    const float* x    = (const float*)d_in[0];
    const float* adj  = (const float*)d_in[1];
    const float* W    = (const float*)d_in[2];
    const float* aL   = (const float*)d_in[3];
    const float* aR   = (const float*)d_in[4];
    const float* bias = (const float*)d_in[5];
    float* out = (float*)d_out;

    pack_adj<<<N / 4, 256>>>(adj);
    project<<<B * (N / 16), 128>>>(x, W, aL, aR);
    armax_k<<<B * H, 256>>>();
    dim3 grid(N / MT, B * H);
    attn<<<grid, 256>>>(bias, out);
}

// round 7
// speedup vs baseline: 1.1619x; 1.1619x over previous
#include <cuda_runtime.h>
#include <cstdint>

// Problem dims (fixed by dataset)
constexpr int B = 4, N = 2048, F = 128, H = 4, D = 32;
constexpr int MT = 64;                  // m rows per attn block
constexpr int KT = 32;                  // k (node) cols per tile
constexpr int HHSTR = 40;               // Hs row stride (words); conflict-free B frags
constexpr float LOG2E = 1.4426950408889634f;

// Scratch (device globals: no allocation allowed)
__device__ __align__(16) float g_h[B * H * N * D];   // [bh][n][d], tf32-rounded
__device__ float g_al[B * H * N];                    // pre-scaled by log2e
__device__ __align__(8) float2 g_ar2[B * H * N];     // (ar, 0.2*ar), log2e-scaled
__device__ unsigned g_armax_u[B * H];                // order-encoded max of ar
__device__ unsigned g_bits[N * (N / 32)];            // adjacency bitmask

// ---------------------------------------------------------------------------
// helpers
// ---------------------------------------------------------------------------
__device__ __forceinline__ float ex2f(float x) {
    float r; asm("ex2.approx.f32 %0, %1;" : "=f"(r) : "f"(x)); return r;
}
__device__ __forceinline__ uint32_t tf32u(float x) {   // round-to-nearest tf32
    uint32_t u; asm("cvt.rna.tf32.f32 %0, %1;" : "=r"(u) : "f"(x));
    return u;
}
__device__ __forceinline__ void ffma2(unsigned long long& d,
                                      unsigned long long a,
                                      unsigned long long b) {
    asm("fma.rn.f32x2 %0, %1, %2, %0;" : "+l"(d) : "l"(a), "l"(b));
}
__device__ __forceinline__ unsigned long long add2(unsigned long long a,
                                                   unsigned long long b) {
    unsigned long long r;
    asm("add.rn.f32x2 %0, %1, %2;" : "=l"(r) : "l"(a), "l"(b));
    return r;
}
__device__ __forceinline__ unsigned long long pk2(float lo, float hi) {
    unsigned long long r;
    asm("mov.b64 %0, {%1, %2};" : "=l"(r)
        : "r"(__float_as_uint(lo)), "r"(__float_as_uint(hi)));
    return r;
}
__device__ __forceinline__ void upk2(unsigned long long v, float& lo, float& hi) {
    unsigned a, b;
    asm("mov.b64 {%0, %1}, %2;" : "=r"(a), "=r"(b) : "l"(v));
    lo = __uint_as_float(a); hi = __uint_as_float(b);
}
__device__ __forceinline__ void mma_tf32(float c[4], uint32_t a0, uint32_t a1,
                                         uint32_t a2, uint32_t a3,
                                         uint32_t b0, uint32_t b1) {
    asm volatile(
        "mma.sync.aligned.m16n8k8.row.col.f32.tf32.tf32.f32 "
        "{%0,%1,%2,%3}, {%4,%5,%6,%7}, {%8,%9}, {%0,%1,%2,%3};"
        : "+f"(c[0]), "+f"(c[1]), "+f"(c[2]), "+f"(c[3])
        : "r"(a0), "r"(a1), "r"(a2), "r"(a3), "r"(b0), "r"(b1));
}

// ---------------------------------------------------------------------------
// Kernel 0: pack adjacency (float 0/1) into bitmask; zero armax accumulators.
// ---------------------------------------------------------------------------
__global__ __launch_bounds__(256) void pack_adj(const float* __restrict__ adj) {
    if (blockIdx.x == 0 && threadIdx.x < B * H) g_armax_u[threadIdx.x] = 0u;
    int warp = threadIdx.x >> 5, lane = threadIdx.x & 31;
    int m = blockIdx.x * 4 + (warp >> 1);
    int hf = warp & 1;
    const float* row = adj + (size_t)m * N + hf * (N / 2);
    unsigned* dst = g_bits + m * (N / 32) + hf * (N / 64);
    #pragma unroll 8
    for (int g = 0; g < N / 64; ++g) {
        float v = row[g * 32 + lane];
        unsigned word = __ballot_sync(0xFFFFFFFFu, v > 0.5f);
        if (lane == 0) dst[g] = word;
    }
}

// ---------------------------------------------------------------------------
// Kernel 1: h = x@W (tf32-rounded store); al/ar via smem-transpose reduction;
// armax via order-encoded atomicMax.
// block = (b, 16 n). 128 threads = (head, d).
// ---------------------------------------------------------------------------
__global__ __launch_bounds__(128) void project(const float* __restrict__ x,
                                               const float* __restrict__ Wm,
                                               const float* __restrict__ aL,
                                               const float* __restrict__ aR) {
    __shared__ __align__(16) float xs[F * 16];   // [f][n] transposed, 8KB
    __shared__ float red[4][16][33];             // full-precision h for al/ar
    const int b = blockIdx.x >> 7;
    const int n0 = (blockIdx.x & 127) * 16;
    const int tid = threadIdx.x;

    {   // load x tile transposed
        const float4* xr = (const float4*)(x + ((size_t)b * N + n0) * F);
        #pragma unroll
        for (int i = tid; i < 16 * (F / 4); i += 128) {
            int n = i >> 5, fq = i & 31;            // F/4 = 32
            float4 v = xr[(size_t)n * 32 + fq];
            xs[(fq * 4 + 0) * 16 + n] = v.x;
            xs[(fq * 4 + 1) * 16 + n] = v.y;
            xs[(fq * 4 + 2) * 16 + n] = v.z;
            xs[(fq * 4 + 3) * 16 + n] = v.w;
        }
    }
    __syncthreads();

    const int hh = tid >> 5, d = tid & 31, lane = tid & 31;
    unsigned long long accp[8];
    #pragma unroll
    for (int i = 0; i < 8; ++i) accp[i] = 0ull;

    const float* Wp = Wm + (size_t)(hh * F) * D + d;
    #pragma unroll 4
    for (int f = 0; f < F; ++f) {
        float w = __ldg(Wp + (size_t)f * D);
        unsigned long long wp = pk2(w, w);
        const ulonglong2* xv = (const ulonglong2*)(xs + f * 16);
        #pragma unroll
        for (int q = 0; q < 4; ++q) {
            ulonglong2 u = xv[q];
            ffma2(accp[q * 2 + 0], u.x, wp);
            ffma2(accp[q * 2 + 1], u.y, wp);
        }
    }

    const size_t base = (size_t)(b * H + hh) * N + n0;
    #pragma unroll
    for (int i = 0; i < 8; ++i) {
        float a0, a1;
        upk2(accp[i], a0, a1);
        red[hh][2 * i][d]     = a0;
        red[hh][2 * i + 1][d] = a1;
        g_h[(base + 2 * i) * D + d]     = __uint_as_float(tf32u(a0));
        g_h[(base + 2 * i + 1) * D + d] = __uint_as_float(tf32u(a1));
    }
    __syncthreads();

    // al/ar: thread (hh, n=lane>>1, lr=lane&1) reduces over d
    {
        const int n = lane >> 1, lr = lane & 1;
        const float* av = (lr ? aR : aL) + hh * D;
        float dot = 0.f;
        #pragma unroll 8
        for (int dd = 0; dd < 32; ++dd)
            dot = fmaf(red[hh][n][dd], __ldg(av + dd), dot);
        dot *= LOG2E;
        const size_t idx = (size_t)(b * H + hh) * N + n0 + n;
        if (lr == 0) g_al[idx] = dot;
        else         g_ar2[idx] = make_float2(dot, 0.2f * dot);
        // order-encoded max of ar over this warp's 16 values -> atomicMax
        unsigned bits = __float_as_uint(dot);
        unsigned key = ((int)bits >= 0) ? (bits | 0x80000000u) : ~bits;
        key = lr ? key : 0u;
        #pragma unroll
        for (int o = 2; o <= 16; o <<= 1)
            key = max(key, __shfl_xor_sync(0xFFFFFFFFu, key, o));
        if (lane == 1) atomicMax(&g_armax_u[b * H + hh], key);
    }
}

// ---------------------------------------------------------------------------
// Kernel 2: fused masked-softmax attention via mma.sync m16n8k8 tf32.
// Block = (b,h, 64 m rows), 8 warps, split-K halves. Per element:
// ADD2 (leaky both branches, M folded) + FMNMX + EX2 + masked-select; p fed
// raw to HMMA (HW tf32-truncation); S accumulated by ones-B HMMA from the
// SAME registers -> exact normalization consistency, no shuffles.
// ---------------------------------------------------------------------------
__global__ __launch_bounds__(256) void attn(const float* __restrict__ bias,
                                            float* __restrict__ out) {
    __shared__ __align__(16) float Hs[2][2][32 * HHSTR];   // [half][stage]
    __shared__ __align__(8) float2 ar2s[2][2][KT];
    __shared__ float Cred[4][16][32];
    __shared__ float Sred[4][16];

    const int tid = threadIdx.x, lane = tid & 31, wid = tid >> 5;
    const int gID = lane >> 2, tIG = lane & 3;
    const int half = wid >> 2, w4 = wid & 3;
    const int bh = blockIdx.y, b = bh >> 2, h = bh & 3;
    const int m0 = blockIdx.x * MT;
    const int gm0 = m0 + w4 * 16 + gID;
    const int gm1 = gm0 + 8;

    unsigned long long rc0, rc1;     // packed (al-M, 0.2al-M) per row
    {
        unsigned k = g_armax_u[bh];
        float armax = (k & 0x80000000u) ? __uint_as_float(k & 0x7FFFFFFFu)
                                        : __uint_as_float(~k);
        float al0 = g_al[(size_t)bh * N + gm0];
        float al1 = g_al[(size_t)bh * N + gm1];
        float t0 = al0 + armax, t1 = al1 + armax;
        float M0 = fmaxf(t0, 0.2f * t0);     // leaky upper bound (monotone)
        float M1 = fmaxf(t1, 0.2f * t1);
        rc0 = pk2(al0 - M0, 0.2f * al0 - M0);
        rc1 = pk2(al1 - M1, 0.2f * al1 - M1);
    }

    float c[4][4], cS[4];
    #pragma unroll
    for (int nt = 0; nt < 4; ++nt) {
        cS[nt] = 0.f;
        #pragma unroll
        for (int i = 0; i < 4; ++i) c[nt][i] = 0.f;
    }

    const float* hb = g_h + (size_t)bh * N * D;
    const float2* arp = g_ar2 + (size_t)bh * N;
    const unsigned* bp0 = g_bits + (size_t)gm0 * (N / 32);
    const unsigned* bp1 = g_bits + (size_t)gm1 * (N / 32);

    // staging map: 128 threads per half stage 32 rows x 32 floats (pure copy)
    const int tid128 = tid & 127;
    const int srow = tid128 >> 2, sseg = tid128 & 3;
    const int t_base = half * 32;

    {   // prologue: stage tile t_base into buffer 0
        const float* src = hb + (size_t)(t_base * 32 + srow) * D;
        *(float4*)&Hs[half][0][srow * HHSTR + sseg * 4] =
            *(const float4*)(src + sseg * 4);
        *(float4*)&Hs[half][0][srow * HHSTR + (sseg + 4) * 4] =
            *(const float4*)(src + (sseg + 4) * 4);
        if (tid128 < KT) ar2s[half][0][tid128] = __ldg(arp + t_base * 32 + tid128);
    }
    __syncthreads();

    for (int i = 0; i < 32; ++i) {
        const int s = i & 1;
        // ---- stage next tile into other buffer ----
        if (i + 1 < 32) {
            const int tn = t_base + i + 1;
            const float* src = hb + (size_t)(tn * 32 + srow) * D;
            float* dst = Hs[half][s ^ 1];
            *(float4*)&dst[srow * HHSTR + sseg * 4] =
                *(const float4*)(src + sseg * 4);
            *(float4*)&dst[srow * HHSTR + (sseg + 4) * 4] =
                *(const float4*)(src + (sseg + 4) * 4);
            if (tid128 < KT)
                ar2s[half][s ^ 1][tid128] = __ldg(arp + tn * 32 + tid128);
        }
        // ---- compute on current buffer ----
        const int tt = t_base + i;
        const unsigned s0w = __ldg(bp0 + tt) >> tIG;
        const unsigned s1w = __ldg(bp1 + tt) >> tIG;
        const float* hs = Hs[half][s];
        const float2* ars = ar2s[half][s];

        #pragma unroll
        for (int kc = 0; kc < 4; ++kc) {
            const unsigned long long avA =
                *(const unsigned long long*)&ars[kc * 8 + tIG];
            const unsigned long long avB =
                *(const unsigned long long*)&ars[kc * 8 + tIG + 4];
            unsigned long long uA0 = add2(rc0, avA);
            unsigned long long uA1 = add2(rc1, avA);
            unsigned long long uB0 = add2(rc0, avB);
            unsigned long long uB1 = add2(rc1, avB);
            float u, v, e00, e10, e01, e11;
            upk2(uA0, u, v); e00 = ex2f(fmaxf(u, v));
            upk2(uA1, u, v); e10 = ex2f(fmaxf(u, v));
            upk2(uB0, u, v); e01 = ex2f(fmaxf(u, v));
            upk2(uB1, u, v); e11 = ex2f(fmaxf(u, v));
            if (!(s0w & (1u << (kc * 8))))      e00 = 0.f;
            if (!(s1w & (1u << (kc * 8))))      e10 = 0.f;
            if (!(s0w & (1u << (kc * 8 + 4))))  e01 = 0.f;
            if (!(s1w & (1u << (kc * 8 + 4))))  e11 = 0.f;
            const uint32_t a0 = __float_as_uint(e00);
            const uint32_t a1 = __float_as_uint(e10);
            const uint32_t a2 = __float_as_uint(e01);
            const uint32_t a3 = __float_as_uint(e11);

            const float* hA = hs + (kc * 8 + tIG) * HHSTR + gID;
            const float* hB = hA + 4 * HHSTR;
            #pragma unroll
            for (int nt = 0; nt < 4; ++nt)
                mma_tf32(c[nt], a0, a1, a2, a3,
                         __float_as_uint(hA[nt * 8]),
                         __float_as_uint(hB[nt * 8]));
            // row sums from the SAME a-registers (ones-B)
            mma_tf32(cS, a0, a1, a2, a3, 0x3f800000u, 0x3f800000u);
        }
        __syncthreads();
    }

    // ---- cross-half reduction (S lives in cS[0]=row gm0, cS[2]=row gm1) ----
    if (half == 1) {
        #pragma unroll
        for (int nt = 0; nt < 4; ++nt) {
            *(float2*)&Cred[w4][gID][nt * 8 + tIG * 2]     = make_float2(c[nt][0], c[nt][1]);
            *(float2*)&Cred[w4][gID + 8][nt * 8 + tIG * 2] = make_float2(c[nt][2], c[nt][3]);
        }
        if (tIG == 0) { Sred[w4][gID] = cS[0]; Sred[w4][gID + 8] = cS[2]; }
    }
    __syncthreads();
    if (half == 1) return;

    const float inv0 = 1.f / (cS[0] + Sred[w4][gID]);
    const float inv1 = 1.f / (cS[2] + Sred[w4][gID + 8]);

    // ---- epilogue: /S, +bias, ELU, store (B,N,H*D) ----
    float* o0 = out + ((size_t)b * N + gm0) * (H * D) + h * D + tIG * 2;
    float* o1 = out + ((size_t)b * N + gm1) * (H * D) + h * D + tIG * 2;
    const float* bp = bias + h * D + tIG * 2;
    #pragma unroll
    for (int nt = 0; nt < 4; ++nt) {
        float2 p0 = *(float2*)&Cred[w4][gID][nt * 8 + tIG * 2];
        float2 p1 = *(float2*)&Cred[w4][gID + 8][nt * 8 + tIG * 2];
        float2 bb = *(const float2*)(bp + nt * 8);
        float v00 = (c[nt][0] + p0.x) * inv0 + bb.x;
        float v01 = (c[nt][1] + p0.y) * inv0 + bb.y;
        float v10 = (c[nt][2] + p1.x) * inv1 + bb.x;
        float v11 = (c[nt][3] + p1.y) * inv1 + bb.y;
        float2 r0, r1;
        r0.x = v00 > 0.f ? v00 : expm1f(v00);
        r0.y = v01 > 0.f ? v01 : expm1f(v01);
        r1.x = v10 > 0.f ? v10 : expm1f(v10);
        r1.y = v11 > 0.f ? v11 : expm1f(v11);
        *(float2*)(o0 + nt * 8) = r0;
        *(float2*)(o1 + nt * 8) = r1;
    }
}

// ---------------------------------------------------------------------------
extern "C" void kernel_launch(void* const* d_in, const int* in_sizes, int n_in,
                              void* d_out, int out_size) {
    const float* x    = (const float*)d_in[0];
    const float* adj  = (const float*)d_in[1];
    const float* W    = (const float*)d_in[2];
    const float* aL   = (const float*)d_in[3];
    const float* aR   = (const float*)d_in[4];
    const float* bias = (const float*)d_in[5];
    float* out = (float*)d_out;

    pack_adj<<<N / 4, 256>>>(adj);
    project<<<B * (N / 16), 128>>>(x, W, aL, aR);
    dim3 grid(N / MT, B * H);
    attn<<<grid, 256>>>(bias, out);
}